// round 9
// baseline (speedup 1.0000x reference)
#include <cuda_runtime.h>
#include <cstdint>
#include <math.h>

#define BB 8
#define NN 2048
#define EE 128
#define HH 4
typedef unsigned short USH;

// ---------------- limb-plane scratch (device globals) ----------------
static __device__ USH g_xp   [3ull *  2097152];   // x      [b][n][128]
static __device__ USH g_w1p  [3ull *   262144];   // W1     [128][2048]
static __device__ USH g_wqp  [3ull *    65536];   // wqW    [512][128]
static __device__ USH g_wvp  [3ull *    65536];   // wvW    [512][128]
static __device__ USH g_w2p  [2ull *    65536];   // W2     [128][512]
static __device__ USH g_infop[3ull * 33554432];   // info   [b][2048][2048]
static __device__ USH g_embp [3ull *  2097152];   // emb    [b][n][128]
static __device__ USH g_qp   [3ull *  8388608];   // q      [b][n][512]
static __device__ USH g_vp   [3ull *  8388608];   // v      [b][n][512]
static __device__ USH g_vtp  [3ull *  8388608];   // vt     [z][f][2048]
static __device__ USH g_mtp  [3ull *  8388608];   // mt     [z][n][128]
static __device__ USH g_attnp[2ull * 134217728];  // attn   [z][2048][2048]
static __device__ USH g_hcatp[2ull *  8388608];   // hcat   [b][n][512]

__device__ __forceinline__ uint32_t smem_u32(const void* p) {
    uint32_t a;
    asm("{ .reg .u64 t; cvta.to.shared.u64 t, %1; cvt.u32.u64 %0, t; }" : "=r"(a) : "l"(p));
    return a;
}
__device__ __forceinline__ uint32_t sw64(uint32_t o) { return o ^ ((o >> 3) & 0x30); }

__device__ __forceinline__ void ldmx4(uint32_t* r, uint32_t addr) {
    asm volatile("ldmatrix.sync.aligned.m8n8.x4.shared.b16 {%0,%1,%2,%3}, [%4];"
                 : "=r"(r[0]), "=r"(r[1]), "=r"(r[2]), "=r"(r[3]) : "r"(addr));
}
__device__ __forceinline__ void mma16816(float* d, const uint32_t* a, const uint32_t* b) {
    asm volatile("mma.sync.aligned.m16n8k16.row.col.f32.bf16.bf16.f32 "
                 "{%0,%1,%2,%3}, {%4,%5,%6,%7}, {%8,%9}, {%0,%1,%2,%3};"
                 : "+f"(d[0]), "+f"(d[1]), "+f"(d[2]), "+f"(d[3])
                 : "r"(a[0]), "r"(a[1]), "r"(a[2]), "r"(a[3]), "r"(b[0]), "r"(b[1]));
}
__device__ __forceinline__ void cp16(uint32_t d, const void* s) {
    asm volatile("cp.async.ca.shared.global [%0], [%1], 16;" :: "r"(d), "l"(s));
}
#define CP_COMMIT asm volatile("cp.async.commit_group;")

// exact truncation split of a float pair into packed bf16x2 limbs
template <int NL>
__device__ __forceinline__ void split2(float f0, float f1, uint32_t& o0, uint32_t& o1, uint32_t& o2) {
    uint32_t u0 = __float_as_uint(f0), u1 = __float_as_uint(f1);
    float a0 = __uint_as_float(u0 & 0xFFFF0000u), a1 = __uint_as_float(u1 & 0xFFFF0000u);
    float r0 = f0 - a0, r1 = f1 - a1;                      // exact
    uint32_t v0 = __float_as_uint(r0), v1 = __float_as_uint(r1);
    o0 = __byte_perm(u0, u1, 0x7632);
    o1 = __byte_perm(v0, v1, 0x7632);
    if (NL == 3) {
        float b0 = __uint_as_float(v0 & 0xFFFF0000u), b1 = __uint_as_float(v1 & 0xFFFF0000u);
        o2 = __byte_perm(__float_as_uint(r0 - b0), __float_as_uint(r1 - b1), 0x7632); // exact
    }
}

// elementwise fp32 -> NL limb planes (plane stride = cnt)
template <int NL>
__global__ void split_k(const float* __restrict__ s, USH* __restrict__ d, size_t cnt) {
    size_t pairs = cnt >> 1;
    uint32_t* d0 = (uint32_t*)d;
    uint32_t* d1 = (uint32_t*)(d + cnt);
    uint32_t* d2 = (uint32_t*)(d + 2 * cnt);
    for (size_t i = (size_t)blockIdx.x * blockDim.x + threadIdx.x; i < pairs;
         i += (size_t)gridDim.x * blockDim.x) {
        float2 f = ((const float2*)s)[i];
        uint32_t p0, p1, p2;
        split2<NL>(f.x, f.y, p0, p1, p2);
        d0[i] = p0; d1[i] = p1;
        if (NL == 3) d2[i] = p2;
    }
}

// ---------------------------------------------------------------------------
// C tile[128x128] = epi(A*B^T) on pre-split bf16 limb planes.
// A planes [M x K] (lda), B planes [Nn x K] (ldb), K-contiguous bf16.
// NL=3 -> 6 limb products (~fp32), NL=2 -> 3 products (~2^-17).
// 512 thr, 4x4 warp grid (32x32 warp tiles), BK=32, 3-stage cp.async pipeline.
// sA/sB/sC are PER-Z element strides within one plane; plane pointers passed
// explicitly (A0/A1/A2 etc.).
// ---------------------------------------------------------------------------
template <int NL, int EPI, int WF32, int WNL>
__global__ void __launch_bounds__(512, 1)
gemm_p(const USH* __restrict__ A0, const USH* __restrict__ A1, const USH* __restrict__ A2,
       size_t sA, size_t sA2, int zdA, int lda,
       const USH* __restrict__ B0, const USH* __restrict__ B1, const USH* __restrict__ B2,
       size_t sB, int ldb,
       const float* __restrict__ bias,
       float* __restrict__ C, USH* __restrict__ P0, USH* __restrict__ P1, USH* __restrict__ P2,
       size_t sC, size_t sC2, int zdC, int ldc,
       int K, float alpha)
{
    constexpr int STAGEB = NL * 16384;           // NL A-planes + NL B-planes, 8KB each
    extern __shared__ __align__(128) char sm[];
    const int t = threadIdx.x;
    const int lane = t & 31, warp = t >> 5;
    const int wm = warp >> 2, wn = warp & 3;     // 4x4 warp grid
    const int z = blockIdx.z;
    const int mblk = blockIdx.y * 128, nblk = blockIdx.x * 128;

    const size_t za = (size_t)(z / zdA) * sA + (size_t)(z % zdA) * sA2 + (size_t)mblk * lda;
    const size_t zb = (size_t)z * sB + (size_t)nblk * ldb;
    const size_t zc = (size_t)(z / zdC) * sC + (size_t)(z % zdC) * sC2;
    const USH *A0z = A0 + za, *A1z = A1 + za, *A2z = A2 + za;
    const USH *B0z = B0 + zb, *B1z = B1 + zb, *B2z = B2 + zb;

    const uint32_t sbase = smem_u32(sm);
    const int row = t >> 2, ch = t & 3;          // 128 rows x 4 16B-chunks
    const uint32_t dst_off = sw64((uint32_t)(row * 64 + ch * 16));  // match ldmatrix swizzle
    const size_t goffA = (size_t)row * lda + ch * 8;
    const size_t goffB = (size_t)row * ldb + ch * 8;

#define LOADSTAGE(s, tt) do {                                                  \
        uint32_t _d = sbase + (s) * STAGEB + dst_off;                          \
        size_t _ga = goffA + (size_t)(tt) * 32;                                \
        size_t _gb = goffB + (size_t)(tt) * 32;                                \
        cp16(_d,                 A0z + _ga);                                   \
        cp16(_d + NL * 8192,     B0z + _gb);                                   \
        cp16(_d + 8192,          A1z + _ga);                                   \
        cp16(_d + NL * 8192 + 8192, B1z + _gb);                                \
        if (NL == 3) {                                                         \
            cp16(_d + 16384,             A2z + _ga);                           \
            cp16(_d + NL * 8192 + 16384, B2z + _gb);                           \
        }                                                                      \
    } while (0)

    float acc[2][4][4];
#pragma unroll
    for (int mi = 0; mi < 2; mi++)
#pragma unroll
        for (int ni = 0; ni < 4; ni++)
#pragma unroll
            for (int c = 0; c < 4; c++) acc[mi][ni][c] = 0.f;

    // ldmatrix lane->address precompute
    const int a_row = wm * 32 + (lane & 15);
    const int a_kb  = (lane >> 4) << 4;
    const int b_row = wn * 32 + (lane & 7) + ((lane & 16) ? 8 : 0);
    const int b_kb  = (lane & 8) ? 16 : 0;

    const int T = K >> 5;
    LOADSTAGE(0, 0); CP_COMMIT;
    if (T > 1) { LOADSTAGE(1, 1); CP_COMMIT; }

    for (int tt = 0; tt < T; tt++) {
        const int s = tt % 3;
        if (tt + 2 <= T) asm volatile("cp.async.wait_group 1;");
        else             asm volatile("cp.async.wait_group 0;");
        __syncthreads();
        if (tt + 2 < T) { LOADSTAGE((tt + 2) % 3, tt + 2); CP_COMMIT; }

        const uint32_t sbb = sbase + s * STAGEB;
#pragma unroll
        for (int ks = 0; ks < 2; ks++) {
#pragma unroll
            for (int ia = 0; ia < NL; ia++) {
                uint32_t afr[2][4];
                uint32_t ab = sbb + ia * 8192;
#pragma unroll
                for (int mi = 0; mi < 2; mi++)
                    ldmx4(afr[mi], ab + sw64((uint32_t)((a_row + mi * 16) * 64 + ks * 32 + a_kb)));
#pragma unroll
                for (int ib = 0; ib < NL - ia; ib++) {
                    uint32_t bfr[4][2];
                    uint32_t bb = sbb + NL * 8192 + ib * 8192;
#pragma unroll
                    for (int nj = 0; nj < 2; nj++) {
                        uint32_t r[4];
                        ldmx4(r, bb + sw64((uint32_t)((b_row + nj * 16) * 64 + ks * 32 + b_kb)));
                        bfr[nj * 2][0] = r[0]; bfr[nj * 2][1] = r[1];
                        bfr[nj * 2 + 1][0] = r[2]; bfr[nj * 2 + 1][1] = r[3];
                    }
#pragma unroll
                    for (int mi = 0; mi < 2; mi++)
#pragma unroll
                        for (int ni = 0; ni < 4; ni++)
                            mma16816(acc[mi][ni], afr[mi], bfr[ni]);
                }
            }
        }
        __syncthreads();
    }

    // epilogue
    const int r0 = mblk + wm * 32 + (lane >> 2);
    const int c0 = nblk + wn * 32 + (lane & 3) * 2;
#pragma unroll
    for (int mi = 0; mi < 2; mi++) {
#pragma unroll
        for (int ni = 0; ni < 4; ni++) {
            int col = c0 + ni * 8;
            float o[4];
#pragma unroll
            for (int c = 0; c < 4; c++) {
                float vv = acc[mi][ni][c];
                if (EPI == 1) vv += __ldg(&bias[col + (c & 1)]);
                else if (EPI == 2) {
                    float ax = fabsf(vv * alpha);
                    float th = 1.f - __fdividef(2.f, __expf(2.f * ax) + 1.f);
                    vv = copysignf(th, vv);
                } else if (EPI == 3) {
                    vv += __ldg(&bias[col + (c & 1)]);
                    vv = vv > 0.f ? vv : 0.f;
                }
                o[c] = vv;
            }
            size_t e0 = zc + (size_t)(r0 + mi * 16) * ldc + col;
            size_t e1 = zc + (size_t)(r0 + mi * 16 + 8) * ldc + col;
            if (WF32) {
                *(float2*)&C[e0] = make_float2(o[0], o[1]);
                *(float2*)&C[e1] = make_float2(o[2], o[3]);
            }
            if (WNL) {
                uint32_t p0, p1, p2;
                split2<WNL>(o[0], o[1], p0, p1, p2);
                ((uint32_t*)P0)[e0 >> 1] = p0;
                ((uint32_t*)P1)[e0 >> 1] = p1;
                if (WNL == 3) ((uint32_t*)P2)[e0 >> 1] = p2;
                split2<WNL>(o[2], o[3], p0, p1, p2);
                ((uint32_t*)P0)[e1 >> 1] = p0;
                ((uint32_t*)P1)[e1 >> 1] = p1;
                if (WNL == 3) ((uint32_t*)P2)[e1 >> 1] = p2;
            }
        }
    }
#undef LOADSTAGE
}

// v planes [p][b][n][512] -> vt planes [p][z][f][2048]
#define VCNT 8388608ull
__global__ void transpose_vp(const USH* __restrict__ s, USH* __restrict__ d) {
    __shared__ USH tl[32][34];
    const int gz = blockIdx.z;
    const int plane = gz >> 5, zz = gz & 31, b = zz >> 2, h = zz & 3;
    const int n0 = blockIdx.x * 32, f0 = blockIdx.y * 32;
    const USH* src = s + plane * VCNT + (size_t)b * NN * 512 + (size_t)h * 128;
    USH* dst = d + plane * VCNT + (size_t)zz * EE * NN;
    const int tx = threadIdx.x, ty = threadIdx.y;
#pragma unroll
    for (int i = 0; i < 32; i += 8)
        tl[ty + i][tx] = src[(size_t)(n0 + ty + i) * 512 + f0 + tx];
    __syncthreads();
#pragma unroll
    for (int i = 0; i < 32; i += 8)
        dst[(size_t)(f0 + ty + i) * NN + n0 + tx] = tl[tx][ty + i];
}

extern "C" void kernel_launch(void* const* d_in, const int* in_sizes, int n_in,
                              void* d_out, int out_size)
{
    const float* x   = (const float*)d_in[0];
    const float* W1  = (const float*)d_in[1];
    const float* b1  = (const float*)d_in[2];
    const float* wqW = (const float*)d_in[3];
    const float* wqb = (const float*)d_in[4];
    // d_in[5], d_in[6]: wk -- dead in the reference
    const float* wvW = (const float*)d_in[7];
    const float* wvb = (const float*)d_in[8];
    const float* W2  = (const float*)d_in[9];
    const float* b2  = (const float*)d_in[10];
    float* out = (float*)d_out;

    USH *xp, *w1p, *wqp, *wvp, *w2p, *infop, *embp, *qp, *vp, *vtp, *mtp, *attnp, *hcatp;
    cudaGetSymbolAddress((void**)&xp,    g_xp);
    cudaGetSymbolAddress((void**)&w1p,   g_w1p);
    cudaGetSymbolAddress((void**)&wqp,   g_wqp);
    cudaGetSymbolAddress((void**)&wvp,   g_wvp);
    cudaGetSymbolAddress((void**)&w2p,   g_w2p);
    cudaGetSymbolAddress((void**)&infop, g_infop);
    cudaGetSymbolAddress((void**)&embp,  g_embp);
    cudaGetSymbolAddress((void**)&qp,    g_qp);
    cudaGetSymbolAddress((void**)&vp,    g_vp);
    cudaGetSymbolAddress((void**)&vtp,   g_vtp);
    cudaGetSymbolAddress((void**)&mtp,   g_mtp);
    cudaGetSymbolAddress((void**)&attnp, g_attnp);
    cudaGetSymbolAddress((void**)&hcatp, g_hcatp);

    const int SM3 = 3 * 3 * 16384;   // 144KB
    const int SM2 = 3 * 2 * 16384;   //  96KB
    cudaFuncSetAttribute(gemm_p<3,0,0,3>, cudaFuncAttributeMaxDynamicSharedMemorySize, SM3);
    cudaFuncSetAttribute(gemm_p<3,1,0,3>, cudaFuncAttributeMaxDynamicSharedMemorySize, SM3);
    cudaFuncSetAttribute(gemm_p<3,2,0,2>, cudaFuncAttributeMaxDynamicSharedMemorySize, SM3);
    cudaFuncSetAttribute(gemm_p<2,0,0,2>, cudaFuncAttributeMaxDynamicSharedMemorySize, SM2);
    cudaFuncSetAttribute(gemm_p<2,3,1,0>, cudaFuncAttributeMaxDynamicSharedMemorySize, SM2);

    const float alpha = 0.08838834764831843f;   // 1/sqrt(128)
    // plane strides (total element counts)
    const size_t XC = 2097152, W1C = 262144, WQC = 65536, IC = 33554432;
    const size_t QC = 8388608, AC = 134217728;
    // per-z element strides within one plane
    const size_t ZX = (size_t)NN * EE;      //  262144 (x/emb per batch)
    const size_t ZI = (size_t)NN * NN;      // 4194304 (info per batch, attn per z)
    const size_t ZQ = (size_t)NN * 512;     // 1048576 (q/v/hcat per batch)
    const size_t ZV = (size_t)EE * NN;      //  262144 (vt/mt per z)

    // input conversions
    split_k<3><<<2048, 256>>>(x,   xp,  XC);
    split_k<3><<<512,  256>>>(W1,  w1p, W1C);
    split_k<3><<<128,  256>>>(wqW, wqp, WQC);
    split_k<3><<<128,  256>>>(wvW, wvp, WQC);
    split_k<2><<<128,  256>>>(W2,  w2p, WQC);

    // S1: info[b] = x_b @ x_b^T                          K=128
    gemm_p<3,0,0,3><<<dim3(16,16,BB), 512, SM3>>>(
        xp, xp+XC, xp+2*XC, ZX, 0, 1, EE,
        xp, xp+XC, xp+2*XC, ZX, EE, nullptr,
        nullptr, infop, infop+IC, infop+2*IC, ZI, 0, 1, NN, EE, 0.f);

    // S2: emb[b] = info_b @ W1^T + b1                    K=2048
    gemm_p<3,1,0,3><<<dim3(1,16,BB), 512, SM3>>>(
        infop, infop+IC, infop+2*IC, ZI, 0, 1, NN,
        w1p, w1p+W1C, w1p+2*W1C, 0, NN, b1,
        nullptr, embp, embp+XC, embp+2*XC, ZX, 0, 1, EE, NN, 0.f);

    // S3: q/v (all heads) = emb_b @ Wcat^T + bcat        K=128
    gemm_p<3,1,0,3><<<dim3(4,16,BB), 512, SM3>>>(
        embp, embp+XC, embp+2*XC, ZX, 0, 1, EE,
        wqp, wqp+WQC, wqp+2*WQC, 0, EE, wqb,
        nullptr, qp, qp+QC, qp+2*QC, ZQ, 0, 1, 512, EE, 0.f);
    gemm_p<3,1,0,3><<<dim3(4,16,BB), 512, SM3>>>(
        embp, embp+XC, embp+2*XC, ZX, 0, 1, EE,
        wvp, wvp+WQC, wvp+2*WQC, 0, EE, wvb,
        nullptr, vp, vp+QC, vp+2*QC, ZQ, 0, 1, 512, EE, 0.f);

    transpose_vp<<<dim3(64,4,96), dim3(32,8)>>>(vp, vtp);

    // S4: mt[z] = info_b @ vt_z^T   (info symmetric)     K=2048
    gemm_p<3,0,0,3><<<dim3(1,16,BB*HH), 512, SM3>>>(
        infop, infop+IC, infop+2*IC, ZI, 0, HH, NN,
        vtp, vtp+QC, vtp+2*QC, ZV, NN, nullptr,
        nullptr, mtp, mtp+QC, mtp+2*QC, ZV, 0, 1, EE, NN, 0.f);

    // S5: attn[z] = tanh((q_z @ mt_z^T) * alpha)         K=128
    gemm_p<3,2,0,2><<<dim3(16,16,BB*HH), 512, SM3>>>(
        qp, qp+QC, qp+2*QC, ZQ, 128, HH, 512,
        mtp, mtp+QC, mtp+2*QC, ZV, EE, nullptr,
        nullptr, attnp, attnp+AC, nullptr, ZI, 0, 1, NN, EE, alpha);

    // S6: hcat[b][n][h*128+f] = attn_z @ vt_z^T          K=2048
    gemm_p<2,0,0,2><<<dim3(1,16,BB*HH), 512, SM2>>>(
        attnp, attnp+AC, nullptr, ZI, 0, 1, NN,
        vtp, vtp+QC, nullptr, ZV, NN, nullptr,
        nullptr, hcatp, hcatp+QC, nullptr, ZQ, 128, HH, 512, NN, 0.f);

    // S7: out[b] = relu(hcat_b @ W2^T + b2)              K=512
    gemm_p<2,3,1,0><<<dim3(1,16,BB), 512, SM2>>>(
        hcatp, hcatp+QC, nullptr, ZQ, 0, 1, 512,
        w2p, w2p+WQC, nullptr, 0, 512, b2,
        out, nullptr, nullptr, nullptr, ZX, 0, 1, EE, 512, 0.f);
}

// round 11
// speedup vs baseline: 1.3310x; 1.3310x over previous
#include <cuda_runtime.h>
#include <cstdint>
#include <math.h>

#define BB 8
#define NN 2048
#define EE 128
#define HH 4

static __device__ float g_info[(size_t)BB * NN * NN];
static __device__ float g_emb [(size_t)BB * NN * EE];
static __device__ float g_q   [(size_t)BB * NN * (HH * EE)];
static __device__ float g_v   [(size_t)BB * NN * (HH * EE)];
static __device__ float g_vt  [(size_t)BB * HH * EE * NN];
static __device__ float g_mt  [(size_t)BB * HH * NN * EE];
static __device__ float g_attn[(size_t)BB * HH * NN * NN];
static __device__ float g_hcat[(size_t)BB * NN * (HH * EE)];

__device__ __forceinline__ uint32_t smem_u32(const void* p) {
    uint32_t a;
    asm("{ .reg .u64 t; cvta.to.shared.u64 t, %1; cvt.u32.u64 %0, t; }" : "=r"(a) : "l"(p));
    return a;
}
__device__ __forceinline__ uint32_t sw64(uint32_t o) { return o ^ ((o >> 3) & 0x30); }

__device__ __forceinline__ void ldmx4(uint32_t* r, uint32_t addr) {
    asm volatile("ldmatrix.sync.aligned.m8n8.x4.shared.b16 {%0,%1,%2,%3}, [%4];"
                 : "=r"(r[0]), "=r"(r[1]), "=r"(r[2]), "=r"(r[3]) : "r"(addr));
}
__device__ __forceinline__ void mma16816(float* d, const uint32_t* a, const uint32_t* b) {
    asm volatile("mma.sync.aligned.m16n8k16.row.col.f32.bf16.bf16.f32 "
                 "{%0,%1,%2,%3}, {%4,%5,%6,%7}, {%8,%9}, {%0,%1,%2,%3};"
                 : "+f"(d[0]), "+f"(d[1]), "+f"(d[2]), "+f"(d[3])
                 : "r"(a[0]), "r"(a[1]), "r"(a[2]), "r"(a[3]), "r"(b[0]), "r"(b[1]));
}

// exact truncation split of a float pair into packed bf16x2 limbs
template <int NL>
__device__ __forceinline__ void split2(float f0, float f1, uint32_t& o0, uint32_t& o1, uint32_t& o2) {
    uint32_t u0 = __float_as_uint(f0), u1 = __float_as_uint(f1);
    float a0 = __uint_as_float(u0 & 0xFFFF0000u), a1 = __uint_as_float(u1 & 0xFFFF0000u);
    float r0 = f0 - a0, r1 = f1 - a1;                      // exact
    uint32_t v0 = __float_as_uint(r0), v1 = __float_as_uint(r1);
    o0 = __byte_perm(u0, u1, 0x7632);
    o1 = __byte_perm(v0, v1, 0x7632);
    if (NL == 3) {
        float b0 = __uint_as_float(v0 & 0xFFFF0000u), b1 = __uint_as_float(v1 & 0xFFFF0000u);
        o2 = __byte_perm(__float_as_uint(r0 - b0), __float_as_uint(r1 - b1), 0x7632); // exact
    }
}

// ---------------------------------------------------------------------------
// Warp-specialized limb GEMM: C tile[128x128] = epi(A*B^T).
// A [M x K] (lda), B [Nn x K] (ldb), fp32, K-contiguous.
// 384 threads: warps 0..7 consumers (32x64 warp tiles, 4x2 grid),
// warps 8..11 producers (LDG fp32 -> exact bf16 limb split -> swizzled STS).
// Double-buffered 2x48KB; named barriers full[b]=1+b, empty[b]=3+b (count 384).
// NL=3 -> 6 limb products (~fp32), NL=2 -> 3 products (~2^-17).
// ---------------------------------------------------------------------------
#define BUFSZ 49152
#define SMEM_BYTES (2 * BUFSZ)

template <int NL, int EPI>
__global__ void __launch_bounds__(384, 1)
gemm_ws(const float* __restrict__ A, size_t sA, size_t sA2, int zdA, int lda,
        const float* __restrict__ B, size_t sB, int ldb,
        const float* __restrict__ bias,
        float* __restrict__ C, size_t sC, size_t sC2, int zdC, int ldc,
        int K, float alpha)
{
    extern __shared__ __align__(128) char sm[];
    const int t = threadIdx.x;
    const int lane = t & 31, warp = t >> 5;
    const int z = blockIdx.z;
    const int mblk = blockIdx.y * 128, nblk = blockIdx.x * 128;

    const float* Az = A + (size_t)(z / zdA) * sA + (size_t)(z % zdA) * sA2 + (size_t)mblk * lda;
    const float* Bz = B + (size_t)z * sB + (size_t)nblk * ldb;
    float* Cz = C + (size_t)(z / zdC) * sC + (size_t)(z % zdC) * sC2;

    const uint32_t sbase = smem_u32(sm);
    const int T = K >> 5;

    if (warp >= 8) {
        // ---------------- producer: 4 warps (1 per SMSP) ----------------
        const int pt   = t - 256;      // 0..127
        const int prow = pt >> 3;      // 0..15 (row within 16-row group)
        const int pch  = pt & 7;       // float4 chunk along K(32)

        for (int tt = 0; tt < T; tt++) {
            const int b = tt & 1;
            if (tt >= 2) asm volatile("bar.sync %0, 384;" :: "r"(3 + b));
            char* buf = sm + b * BUFSZ;
            const float* ap = Az + tt * 32 + pch * 4;
            const float* bp = Bz + tt * 32 + pch * 4;
#pragma unroll
            for (int j = 0; j < 8; j++) {
                const int row = j * 16 + prow;
                float4 fa = *(const float4*)(ap + (size_t)row * lda);
                float4 fb = *(const float4*)(bp + (size_t)row * ldb);
                const uint32_t off = sw64((uint32_t)(row * 64 + pch * 8));
                uint32_t p0, p1, p2, q0, q1, q2;
                split2<NL>(fa.x, fa.y, p0, p1, p2);
                split2<NL>(fa.z, fa.w, q0, q1, q2);
                *(uint2*)(buf + off)        = make_uint2(p0, q0);
                *(uint2*)(buf + 8192 + off) = make_uint2(p1, q1);
                if (NL == 3) *(uint2*)(buf + 16384 + off) = make_uint2(p2, q2);
                split2<NL>(fb.x, fb.y, p0, p1, p2);
                split2<NL>(fb.z, fb.w, q0, q1, q2);
                *(uint2*)(buf + 24576 + off)        = make_uint2(p0, q0);
                *(uint2*)(buf + 24576 + 8192 + off) = make_uint2(p1, q1);
                if (NL == 3) *(uint2*)(buf + 24576 + 16384 + off) = make_uint2(p2, q2);
            }
            asm volatile("bar.arrive %0, 384;" :: "r"(1 + b));
        }
        return;
    }

    // ---------------- consumer: 8 warps, 4x2 grid of 32x64 tiles ----------------
    const int wm = warp >> 1, wn = warp & 1;

    float acc[2][8][4];
#pragma unroll
    for (int mi = 0; mi < 2; mi++)
#pragma unroll
        for (int f = 0; f < 8; f++)
#pragma unroll
            for (int c = 0; c < 4; c++) acc[mi][f][c] = 0.f;

    const int a_row = wm * 32 + (lane & 15);
    const int a_kb  = (lane >> 4) << 4;
    const int b_row = wn * 64 + (lane & 7) + ((lane & 16) ? 8 : 0);
    const int b_kb  = (lane & 8) ? 16 : 0;

    for (int tt = 0; tt < T; tt++) {
        const int b = tt & 1;
        asm volatile("bar.sync %0, 384;" :: "r"(1 + b));
        const uint32_t bufb = sbase + b * BUFSZ;
#pragma unroll
        for (int ks = 0; ks < 2; ks++) {
#pragma unroll
            for (int ia = 0; ia < NL; ia++) {
                uint32_t afr[2][4];
                const uint32_t ab = bufb + ia * 8192;
#pragma unroll
                for (int mi = 0; mi < 2; mi++)
                    ldmx4(afr[mi], ab + sw64((uint32_t)((a_row + mi * 16) * 64 + ks * 32 + a_kb)));
#pragma unroll
                for (int ib = 0; ib < NL - ia; ib++) {
                    uint32_t bfr[8][2];
                    const uint32_t bb = bufb + 24576 + ib * 8192;
#pragma unroll
                    for (int nj = 0; nj < 4; nj++) {
                        uint32_t r[4];
                        ldmx4(r, bb + sw64((uint32_t)((b_row + nj * 16) * 64 + ks * 32 + b_kb)));
                        bfr[nj * 2][0] = r[0]; bfr[nj * 2][1] = r[1];
                        bfr[nj * 2 + 1][0] = r[2]; bfr[nj * 2 + 1][1] = r[3];
                    }
#pragma unroll
                    for (int mi = 0; mi < 2; mi++)
#pragma unroll
                        for (int f = 0; f < 8; f++)
                            mma16816(acc[mi][f], afr[mi], bfr[f]);
                }
            }
        }
        if (tt + 2 < T) asm volatile("bar.arrive %0, 384;" :: "r"(3 + b));
    }

    // epilogue: direct frag stores (float2)
    const int r0 = mblk + wm * 32 + (lane >> 2);
    const int c0 = nblk + wn * 64 + (lane & 3) * 2;
#pragma unroll
    for (int mi = 0; mi < 2; mi++) {
#pragma unroll
        for (int f = 0; f < 8; f++) {
            const int col = c0 + f * 8;
            float o[4];
#pragma unroll
            for (int c = 0; c < 4; c++) {
                float vv = acc[mi][f][c];
                if (EPI == 1) vv += __ldg(&bias[col + (c & 1)]);
                else if (EPI == 2) {
                    float ax = fabsf(vv * alpha);
                    float th = 1.f - __fdividef(2.f, __expf(2.f * ax) + 1.f);
                    vv = copysignf(th, vv);
                } else if (EPI == 3) {
                    vv += __ldg(&bias[col + (c & 1)]);
                    vv = vv > 0.f ? vv : 0.f;
                }
                o[c] = vv;
            }
            *(float2*)&Cz[(size_t)(r0 + mi * 16) * ldc + col]     = make_float2(o[0], o[1]);
            *(float2*)&Cz[(size_t)(r0 + mi * 16 + 8) * ldc + col] = make_float2(o[2], o[3]);
        }
    }
}

// v [b][n][h*128+f] -> vt [z][f][n]
__global__ void transpose_v(const float* __restrict__ v, float* __restrict__ vt) {
    __shared__ float tl[32][33];
    const int z = blockIdx.z, b = z >> 2, h = z & 3;
    const int n0 = blockIdx.x * 32, f0 = blockIdx.y * 32;
    const float* src = v + (size_t)b * NN * 512 + (size_t)h * 128;
    float* dst = vt + (size_t)z * EE * NN;
    const int tx = threadIdx.x, ty = threadIdx.y;
#pragma unroll
    for (int i = 0; i < 32; i += 8)
        tl[ty + i][tx] = src[(size_t)(n0 + ty + i) * 512 + f0 + tx];
    __syncthreads();
#pragma unroll
    for (int i = 0; i < 32; i += 8)
        dst[(size_t)(f0 + ty + i) * NN + n0 + tx] = tl[tx][ty + i];
}

extern "C" void kernel_launch(void* const* d_in, const int* in_sizes, int n_in,
                              void* d_out, int out_size)
{
    const float* x   = (const float*)d_in[0];
    const float* W1  = (const float*)d_in[1];
    const float* b1  = (const float*)d_in[2];
    const float* wqW = (const float*)d_in[3];
    const float* wqb = (const float*)d_in[4];
    // d_in[5], d_in[6]: wk -- dead in the reference
    const float* wvW = (const float*)d_in[7];
    const float* wvb = (const float*)d_in[8];
    const float* W2  = (const float*)d_in[9];
    const float* b2  = (const float*)d_in[10];
    float* out = (float*)d_out;

    float *info, *emb, *q, *v, *vt, *mt, *attn, *hcat;
    cudaGetSymbolAddress((void**)&info, g_info);
    cudaGetSymbolAddress((void**)&emb,  g_emb);
    cudaGetSymbolAddress((void**)&q,    g_q);
    cudaGetSymbolAddress((void**)&v,    g_v);
    cudaGetSymbolAddress((void**)&vt,   g_vt);
    cudaGetSymbolAddress((void**)&mt,   g_mt);
    cudaGetSymbolAddress((void**)&attn, g_attn);
    cudaGetSymbolAddress((void**)&hcat, g_hcat);

    cudaFuncSetAttribute(gemm_ws<3,0>, cudaFuncAttributeMaxDynamicSharedMemorySize, SMEM_BYTES);
    cudaFuncSetAttribute(gemm_ws<3,1>, cudaFuncAttributeMaxDynamicSharedMemorySize, SMEM_BYTES);
    cudaFuncSetAttribute(gemm_ws<3,2>, cudaFuncAttributeMaxDynamicSharedMemorySize, SMEM_BYTES);
    cudaFuncSetAttribute(gemm_ws<2,0>, cudaFuncAttributeMaxDynamicSharedMemorySize, SMEM_BYTES);
    cudaFuncSetAttribute(gemm_ws<2,3>, cudaFuncAttributeMaxDynamicSharedMemorySize, SMEM_BYTES);

    const float alpha = 0.08838834764831843f;  // 1/sqrt(128)

    // S1: info[b] = x_b @ x_b^T                         K=128
    gemm_ws<3,0><<<dim3(16,16,BB), 384, SMEM_BYTES>>>(
        x, (size_t)NN*EE, 0, 1, EE,  x, (size_t)NN*EE, EE,  nullptr,
        info, (size_t)NN*NN, 0, 1, NN,  EE, 0.f);

    // S2: emb[b] = info_b @ W1^T + b1                   K=2048
    gemm_ws<3,1><<<dim3(1,16,BB), 384, SMEM_BYTES>>>(
        info, (size_t)NN*NN, 0, 1, NN,  W1, 0, NN,  b1,
        emb, (size_t)NN*EE, 0, 1, EE,  NN, 0.f);

    // S3: q/v (all heads) = emb_b @ Wcat^T + bcat       K=128
    gemm_ws<3,1><<<dim3(4,16,BB), 384, SMEM_BYTES>>>(
        emb, (size_t)NN*EE, 0, 1, EE,  wqW, 0, EE,  wqb,
        q, (size_t)NN*512, 0, 1, 512,  EE, 0.f);
    gemm_ws<3,1><<<dim3(4,16,BB), 384, SMEM_BYTES>>>(
        emb, (size_t)NN*EE, 0, 1, EE,  wvW, 0, EE,  wvb,
        v, (size_t)NN*512, 0, 1, 512,  EE, 0.f);

    transpose_v<<<dim3(64,4,BB*HH), dim3(32,8)>>>(v, vt);

    // S4: mt[z] = info_b @ vt_z^T  (info symmetric)     K=2048
    gemm_ws<3,0><<<dim3(1,16,BB*HH), 384, SMEM_BYTES>>>(
        info, (size_t)NN*NN, 0, HH, NN,  vt, (size_t)EE*NN, NN,  nullptr,
        mt, (size_t)NN*EE, 0, 1, EE,  NN, 0.f);

    // S5: attn[z] = tanh((q_z @ mt_z^T) * alpha)        K=128
    gemm_ws<3,2><<<dim3(16,16,BB*HH), 384, SMEM_BYTES>>>(
        q, (size_t)NN*512, 128, HH, 512,  mt, (size_t)NN*EE, EE,  nullptr,
        attn, (size_t)NN*NN, 0, 1, NN,  EE, alpha);

    // S6: hcat[b][n][h*128+f] = attn_z @ vt_z^T         K=2048
    gemm_ws<2,0><<<dim3(1,16,BB*HH), 384, SMEM_BYTES>>>(
        attn, (size_t)NN*NN, 0, 1, NN,  vt, (size_t)EE*NN, NN,  nullptr,
        hcat, (size_t)NN*512, 128, HH, 512,  NN, 0.f);

    // S7: out[b] = relu(hcat_b @ W2^T + b2)             K=512
    gemm_ws<2,3><<<dim3(1,16,BB), 384, SMEM_BYTES>>>(
        hcat, (size_t)NN*512, 0, 1, 512,  W2, 0, 512,  b2,
        out, (size_t)NN*EE, 0, 1, EE,  512, 0.f);
}

// round 12
// speedup vs baseline: 1.3583x; 1.0205x over previous
#include <cuda_runtime.h>
#include <cstdint>
#include <math.h>

#define BB 8
#define NN 2048
#define EE 128
#define HH 4

static __device__ float g_info[(size_t)BB * NN * NN];
static __device__ float g_emb [(size_t)BB * NN * EE];
static __device__ float g_q   [(size_t)BB * NN * (HH * EE)];
static __device__ float g_v   [(size_t)BB * NN * (HH * EE)];
static __device__ float g_vt  [(size_t)BB * HH * EE * NN];
static __device__ float g_mt  [(size_t)BB * HH * NN * EE];
static __device__ float g_attn[(size_t)BB * HH * NN * NN];
static __device__ float g_hcat[(size_t)BB * NN * (HH * EE)];

__device__ __forceinline__ uint32_t smem_u32(const void* p) {
    uint32_t a;
    asm("{ .reg .u64 t; cvta.to.shared.u64 t, %1; cvt.u32.u64 %0, t; }" : "=r"(a) : "l"(p));
    return a;
}
__device__ __forceinline__ uint32_t sw64(uint32_t o) { return o ^ ((o >> 3) & 0x30); }

__device__ __forceinline__ void ldmx4(uint32_t* r, uint32_t addr) {
    asm volatile("ldmatrix.sync.aligned.m8n8.x4.shared.b16 {%0,%1,%2,%3}, [%4];"
                 : "=r"(r[0]), "=r"(r[1]), "=r"(r[2]), "=r"(r[3]) : "r"(addr));
}
__device__ __forceinline__ void mma16816(float* d, const uint32_t* a, const uint32_t* b) {
    asm volatile("mma.sync.aligned.m16n8k16.row.col.f32.bf16.bf16.f32 "
                 "{%0,%1,%2,%3}, {%4,%5,%6,%7}, {%8,%9}, {%0,%1,%2,%3};"
                 : "+f"(d[0]), "+f"(d[1]), "+f"(d[2]), "+f"(d[3])
                 : "r"(a[0]), "r"(a[1]), "r"(a[2]), "r"(a[3]), "r"(b[0]), "r"(b[1]));
}

// exact truncation split of a float pair into packed bf16x2 limbs
template <int NL>
__device__ __forceinline__ void split2(float f0, float f1, uint32_t& o0, uint32_t& o1, uint32_t& o2) {
    uint32_t u0 = __float_as_uint(f0), u1 = __float_as_uint(f1);
    float a0 = __uint_as_float(u0 & 0xFFFF0000u), a1 = __uint_as_float(u1 & 0xFFFF0000u);
    float r0 = f0 - a0, r1 = f1 - a1;                      // exact
    uint32_t v0 = __float_as_uint(r0), v1 = __float_as_uint(r1);
    o0 = __byte_perm(u0, u1, 0x7632);
    o1 = __byte_perm(v0, v1, 0x7632);
    if (NL == 3) {
        float b0 = __uint_as_float(v0 & 0xFFFF0000u), b1 = __uint_as_float(v1 & 0xFFFF0000u);
        o2 = __byte_perm(__float_as_uint(r0 - b0), __float_as_uint(r1 - b1), 0x7632); // exact
    }
}

// ---------------------------------------------------------------------------
// Warp-specialized limb GEMM, SMEM-traffic-minimized.
// C tile[128x128] = epi(A*B^T); A [MxK] (lda), B [NnxK] (ldb), fp32 K-contig.
// 256 threads: warps 0..3 consumers (64x64 tiles, 2x2 grid) — per ks-step all
// A-planes + each B-plane loaded ONCE into registers, 6 limb products from
// regs; warps 4..7 producers (LDG -> exact limb split -> swizzled STS).
// Double-buffered 2x48KB; named barriers full[b]=1+b, empty[b]=3+b (count 256).
// ---------------------------------------------------------------------------
#define BUFSZ 49152
#define SMEM_BYTES (2 * BUFSZ)

template <int NL, int EPI>
__global__ void __launch_bounds__(256, 1)
gemm_ws(const float* __restrict__ A, size_t sA, size_t sA2, int zdA, int lda,
        const float* __restrict__ B, size_t sB, int ldb,
        const float* __restrict__ bias,
        float* __restrict__ C, size_t sC, size_t sC2, int zdC, int ldc,
        int K, float alpha)
{
    extern __shared__ __align__(128) char sm[];
    const int t = threadIdx.x;
    const int lane = t & 31, warp = t >> 5;
    const int z = blockIdx.z;
    const int mblk = blockIdx.y * 128, nblk = blockIdx.x * 128;

    const float* Az = A + (size_t)(z / zdA) * sA + (size_t)(z % zdA) * sA2 + (size_t)mblk * lda;
    const float* Bz = B + (size_t)z * sB + (size_t)nblk * ldb;
    float* Cz = C + (size_t)(z / zdC) * sC + (size_t)(z % zdC) * sC2;

    const uint32_t sbase = smem_u32(sm);
    const int T = K >> 5;

    if (warp >= 4) {
        // ---------------- producer: 4 warps ----------------
        const int pt   = t - 128;      // 0..127
        const int prow = pt >> 3;      // 0..15
        const int pch  = pt & 7;       // float4 chunk along K(32)

        for (int tt = 0; tt < T; tt++) {
            const int b = tt & 1;
            if (tt >= 2) asm volatile("bar.sync %0, 256;" :: "r"(3 + b));
            char* buf = sm + b * BUFSZ;
            const float* ap = Az + tt * 32 + pch * 4;
            const float* bp = Bz + tt * 32 + pch * 4;
            float4 fa[8], fb[8];
#pragma unroll
            for (int j = 0; j < 8; j++) {          // front-batched LDGs (MLP 16)
                fa[j] = *(const float4*)(ap + (size_t)(j * 16 + prow) * lda);
                fb[j] = *(const float4*)(bp + (size_t)(j * 16 + prow) * ldb);
            }
#pragma unroll
            for (int j = 0; j < 8; j++) {
                const uint32_t off = sw64((uint32_t)((j * 16 + prow) * 64 + pch * 8));
                uint32_t p0, p1, p2, q0, q1, q2;
                split2<NL>(fa[j].x, fa[j].y, p0, p1, p2);
                split2<NL>(fa[j].z, fa[j].w, q0, q1, q2);
                *(uint2*)(buf + off)        = make_uint2(p0, q0);
                *(uint2*)(buf + 8192 + off) = make_uint2(p1, q1);
                if (NL == 3) *(uint2*)(buf + 16384 + off) = make_uint2(p2, q2);
                split2<NL>(fb[j].x, fb[j].y, p0, p1, p2);
                split2<NL>(fb[j].z, fb[j].w, q0, q1, q2);
                *(uint2*)(buf + 24576 + off)        = make_uint2(p0, q0);
                *(uint2*)(buf + 24576 + 8192 + off) = make_uint2(p1, q1);
                if (NL == 3) *(uint2*)(buf + 24576 + 16384 + off) = make_uint2(p2, q2);
            }
            asm volatile("bar.arrive %0, 256;" :: "r"(1 + b));
        }
        return;
    }

    // ---------------- consumer: 4 warps, 2x2 grid of 64x64 tiles ----------------
    const int wm = warp >> 1, wn = warp & 1;

    float acc[4][8][4];
#pragma unroll
    for (int mi = 0; mi < 4; mi++)
#pragma unroll
        for (int f = 0; f < 8; f++)
#pragma unroll
            for (int c = 0; c < 4; c++) acc[mi][f][c] = 0.f;

    const int a_row = wm * 64 + (lane & 15);
    const int a_kb  = (lane >> 4) << 4;
    const int b_row = wn * 64 + (lane & 7) + ((lane & 16) ? 8 : 0);
    const int b_kb  = (lane & 8) ? 16 : 0;

    for (int tt = 0; tt < T; tt++) {
        const int b = tt & 1;
        asm volatile("bar.sync %0, 256;" :: "r"(1 + b));
        const uint32_t bufb = sbase + b * BUFSZ;
#pragma unroll
        for (int ks = 0; ks < 2; ks++) {
            // load ALL A planes for this ks once (regs)
            uint32_t afr[NL][4][4];
#pragma unroll
            for (int p = 0; p < NL; p++)
#pragma unroll
                for (int mi = 0; mi < 4; mi++)
                    ldmx4(afr[p][mi],
                          bufb + p * 8192 + sw64((uint32_t)((a_row + mi * 16) * 64 + ks * 32 + a_kb)));
            // B planes: load once each, double-buffered in regs
            uint32_t bfr[2][8][2];
#define LOADB(slot, plane) do {                                                \
                const uint32_t _bb = bufb + 24576 + (plane) * 8192;            \
                _Pragma("unroll")                                              \
                for (int nj = 0; nj < 4; nj++) {                               \
                    uint32_t r[4];                                             \
                    ldmx4(r, _bb + sw64((uint32_t)((b_row + nj * 16) * 64 + ks * 32 + b_kb))); \
                    bfr[slot][nj * 2][0] = r[0]; bfr[slot][nj * 2][1] = r[1];  \
                    bfr[slot][nj * 2 + 1][0] = r[2]; bfr[slot][nj * 2 + 1][1] = r[3]; \
                }                                                              \
            } while (0)
            LOADB(0, 0);
#pragma unroll
            for (int ib = 0; ib < NL; ib++) {
                if (ib + 1 < NL) LOADB((ib + 1) & 1, ib + 1);
#pragma unroll
                for (int ia = 0; ia < NL - ib; ia++)
#pragma unroll
                    for (int mi = 0; mi < 4; mi++)
#pragma unroll
                        for (int f = 0; f < 8; f++)
                            mma16816(acc[mi][f], afr[ia][mi], bfr[ib & 1][f]);
            }
#undef LOADB
        }
        if (tt + 2 < T) asm volatile("bar.arrive %0, 256;" :: "r"(3 + b));
    }

    // epilogue: direct frag stores (float2)
    const int r0 = mblk + wm * 64 + (lane >> 2);
    const int c0 = nblk + wn * 64 + (lane & 3) * 2;
#pragma unroll
    for (int mi = 0; mi < 4; mi++) {
#pragma unroll
        for (int f = 0; f < 8; f++) {
            const int col = c0 + f * 8;
            float o[4];
#pragma unroll
            for (int c = 0; c < 4; c++) {
                float vv = acc[mi][f][c];
                if (EPI == 1) vv += __ldg(&bias[col + (c & 1)]);
                else if (EPI == 2) {
                    float ax = fabsf(vv * alpha);
                    float th = 1.f - __fdividef(2.f, __expf(2.f * ax) + 1.f);
                    vv = copysignf(th, vv);
                } else if (EPI == 3) {
                    vv += __ldg(&bias[col + (c & 1)]);
                    vv = vv > 0.f ? vv : 0.f;
                }
                o[c] = vv;
            }
            *(float2*)&Cz[(size_t)(r0 + mi * 16) * ldc + col]     = make_float2(o[0], o[1]);
            *(float2*)&Cz[(size_t)(r0 + mi * 16 + 8) * ldc + col] = make_float2(o[2], o[3]);
        }
    }
}

// v [b][n][h*128+f] -> vt [z][f][n]
__global__ void transpose_v(const float* __restrict__ v, float* __restrict__ vt) {
    __shared__ float tl[32][33];
    const int z = blockIdx.z, b = z >> 2, h = z & 3;
    const int n0 = blockIdx.x * 32, f0 = blockIdx.y * 32;
    const float* src = v + (size_t)b * NN * 512 + (size_t)h * 128;
    float* dst = vt + (size_t)z * EE * NN;
    const int tx = threadIdx.x, ty = threadIdx.y;
#pragma unroll
    for (int i = 0; i < 32; i += 8)
        tl[ty + i][tx] = src[(size_t)(n0 + ty + i) * 512 + f0 + tx];
    __syncthreads();
#pragma unroll
    for (int i = 0; i < 32; i += 8)
        dst[(size_t)(f0 + ty + i) * NN + n0 + tx] = tl[tx][ty + i];
}

extern "C" void kernel_launch(void* const* d_in, const int* in_sizes, int n_in,
                              void* d_out, int out_size)
{
    const float* x   = (const float*)d_in[0];
    const float* W1  = (const float*)d_in[1];
    const float* b1  = (const float*)d_in[2];
    const float* wqW = (const float*)d_in[3];
    const float* wqb = (const float*)d_in[4];
    // d_in[5], d_in[6]: wk -- dead in the reference
    const float* wvW = (const float*)d_in[7];
    const float* wvb = (const float*)d_in[8];
    const float* W2  = (const float*)d_in[9];
    const float* b2  = (const float*)d_in[10];
    float* out = (float*)d_out;

    float *info, *emb, *q, *v, *vt, *mt, *attn, *hcat;
    cudaGetSymbolAddress((void**)&info, g_info);
    cudaGetSymbolAddress((void**)&emb,  g_emb);
    cudaGetSymbolAddress((void**)&q,    g_q);
    cudaGetSymbolAddress((void**)&v,    g_v);
    cudaGetSymbolAddress((void**)&vt,   g_vt);
    cudaGetSymbolAddress((void**)&mt,   g_mt);
    cudaGetSymbolAddress((void**)&attn, g_attn);
    cudaGetSymbolAddress((void**)&hcat, g_hcat);

    cudaFuncSetAttribute(gemm_ws<3,0>, cudaFuncAttributeMaxDynamicSharedMemorySize, SMEM_BYTES);
    cudaFuncSetAttribute(gemm_ws<3,1>, cudaFuncAttributeMaxDynamicSharedMemorySize, SMEM_BYTES);
    cudaFuncSetAttribute(gemm_ws<3,2>, cudaFuncAttributeMaxDynamicSharedMemorySize, SMEM_BYTES);
    cudaFuncSetAttribute(gemm_ws<2,0>, cudaFuncAttributeMaxDynamicSharedMemorySize, SMEM_BYTES);
    cudaFuncSetAttribute(gemm_ws<2,3>, cudaFuncAttributeMaxDynamicSharedMemorySize, SMEM_BYTES);

    const float alpha = 0.08838834764831843f;  // 1/sqrt(128)

    // S1: info[b] = x_b @ x_b^T                         K=128
    gemm_ws<3,0><<<dim3(16,16,BB), 256, SMEM_BYTES>>>(
        x, (size_t)NN*EE, 0, 1, EE,  x, (size_t)NN*EE, EE,  nullptr,
        info, (size_t)NN*NN, 0, 1, NN,  EE, 0.f);

    // S2: emb[b] = info_b @ W1^T + b1                   K=2048
    gemm_ws<3,1><<<dim3(1,16,BB), 256, SMEM_BYTES>>>(
        info, (size_t)NN*NN, 0, 1, NN,  W1, 0, NN,  b1,
        emb, (size_t)NN*EE, 0, 1, EE,  NN, 0.f);

    // S3: q/v (all heads) = emb_b @ Wcat^T + bcat       K=128
    gemm_ws<3,1><<<dim3(4,16,BB), 256, SMEM_BYTES>>>(
        emb, (size_t)NN*EE, 0, 1, EE,  wqW, 0, EE,  wqb,
        q, (size_t)NN*512, 0, 1, 512,  EE, 0.f);
    gemm_ws<3,1><<<dim3(4,16,BB), 256, SMEM_BYTES>>>(
        emb, (size_t)NN*EE, 0, 1, EE,  wvW, 0, EE,  wvb,
        v, (size_t)NN*512, 0, 1, 512,  EE, 0.f);

    transpose_v<<<dim3(64,4,BB*HH), dim3(32,8)>>>(v, vt);

    // S4: mt[z] = info_b @ vt_z^T  (info symmetric)     K=2048
    gemm_ws<3,0><<<dim3(1,16,BB*HH), 256, SMEM_BYTES>>>(
        info, (size_t)NN*NN, 0, HH, NN,  vt, (size_t)EE*NN, NN,  nullptr,
        mt, (size_t)NN*EE, 0, 1, EE,  NN, 0.f);

    // S5: attn[z] = tanh((q_z @ mt_z^T) * alpha)        K=128
    gemm_ws<3,2><<<dim3(16,16,BB*HH), 256, SMEM_BYTES>>>(
        q, (size_t)NN*512, 128, HH, 512,  mt, (size_t)NN*EE, EE,  nullptr,
        attn, (size_t)NN*NN, 0, 1, NN,  EE, alpha);

    // S6: hcat[b][n][h*128+f] = attn_z @ vt_z^T         K=2048
    gemm_ws<2,0><<<dim3(1,16,BB*HH), 256, SMEM_BYTES>>>(
        attn, (size_t)NN*NN, 0, 1, NN,  vt, (size_t)EE*NN, NN,  nullptr,
        hcat, (size_t)NN*512, 128, HH, 512,  NN, 0.f);

    // S7: out[b] = relu(hcat_b @ W2^T + b2)             K=512
    gemm_ws<2,3><<<dim3(1,16,BB), 256, SMEM_BYTES>>>(
        hcat, (size_t)NN*512, 0, 1, 512,  W2, 0, 512,  b2,
        out, (size_t)NN*EE, 0, 1, EE,  512, 0.f);
}

// round 13
// speedup vs baseline: 1.8143x; 1.3357x over previous
#include <cuda_runtime.h>
#include <cstdint>
#include <math.h>

#define BB 8
#define NN 2048
#define EE 128
#define HH 4

static __device__ float g_xt  [(size_t)BB * EE * NN];           // x^T  [b][d][n]
static __device__ float g_u   [(size_t)BB * EE * EE];           // W1 x^T [b][e][d]
static __device__ float g_emb [(size_t)BB * NN * EE];
static __device__ float g_q   [(size_t)BB * NN * (HH * EE)];
static __device__ float g_v   [(size_t)BB * NN * (HH * EE)];
static __device__ float g_vt  [(size_t)BB * HH * EE * NN];      // [z][f][n]
static __device__ float g_wt  [(size_t)BB * HH * EE * EE];      // (x^T v)  [z][d][f]
static __device__ float g_wp  [(size_t)BB * HH * EE * EE];      // (x^T v)^T [z][f][d]
static __device__ float g_mt  [(size_t)BB * HH * NN * EE];
static __device__ float g_attn[(size_t)BB * HH * NN * NN];
static __device__ float g_hcat[(size_t)BB * NN * (HH * EE)];

__device__ __forceinline__ uint32_t smem_u32(const void* p) {
    uint32_t a;
    asm("{ .reg .u64 t; cvta.to.shared.u64 t, %1; cvt.u32.u64 %0, t; }" : "=r"(a) : "l"(p));
    return a;
}
__device__ __forceinline__ uint32_t sw64(uint32_t o) { return o ^ ((o >> 3) & 0x30); }

__device__ __forceinline__ void ldmx4(uint32_t* r, uint32_t addr) {
    asm volatile("ldmatrix.sync.aligned.m8n8.x4.shared.b16 {%0,%1,%2,%3}, [%4];"
                 : "=r"(r[0]), "=r"(r[1]), "=r"(r[2]), "=r"(r[3]) : "r"(addr));
}
__device__ __forceinline__ void mma16816(float* d, const uint32_t* a, const uint32_t* b) {
    asm volatile("mma.sync.aligned.m16n8k16.row.col.f32.bf16.bf16.f32 "
                 "{%0,%1,%2,%3}, {%4,%5,%6,%7}, {%8,%9}, {%0,%1,%2,%3};"
                 : "+f"(d[0]), "+f"(d[1]), "+f"(d[2]), "+f"(d[3])
                 : "r"(a[0]), "r"(a[1]), "r"(a[2]), "r"(a[3]), "r"(b[0]), "r"(b[1]));
}

// exact truncation split of a float pair into packed bf16x2 limbs
template <int NL>
__device__ __forceinline__ void split2(float f0, float f1, uint32_t& o0, uint32_t& o1, uint32_t& o2) {
    uint32_t u0 = __float_as_uint(f0), u1 = __float_as_uint(f1);
    float a0 = __uint_as_float(u0 & 0xFFFF0000u), a1 = __uint_as_float(u1 & 0xFFFF0000u);
    float r0 = f0 - a0, r1 = f1 - a1;                      // exact
    uint32_t v0 = __float_as_uint(r0), v1 = __float_as_uint(r1);
    o0 = __byte_perm(u0, u1, 0x7632);
    o1 = __byte_perm(v0, v1, 0x7632);
    if (NL == 3) {
        float b0 = __uint_as_float(v0 & 0xFFFF0000u), b1 = __uint_as_float(v1 & 0xFFFF0000u);
        o2 = __byte_perm(__float_as_uint(r0 - b0), __float_as_uint(r1 - b1), 0x7632); // exact
    }
}

// ---------------------------------------------------------------------------
// Warp-specialized limb GEMM (unchanged from best round).
// C tile[128x128] = epi(A*B^T); A [MxK] (lda), B [NnxK] (ldb), fp32 K-contig.
// warps 0..3 consumers (64x64 tiles), warps 4..7 producers.
// ---------------------------------------------------------------------------
#define BUFSZ 49152
#define SMEM_BYTES (2 * BUFSZ)

template <int NL, int EPI>
__global__ void __launch_bounds__(256, 1)
gemm_ws(const float* __restrict__ A, size_t sA, size_t sA2, int zdA, int lda,
        const float* __restrict__ B, size_t sB, int ldb,
        const float* __restrict__ bias,
        float* __restrict__ C, size_t sC, size_t sC2, int zdC, int ldc,
        int K, float alpha)
{
    extern __shared__ __align__(128) char sm[];
    const int t = threadIdx.x;
    const int lane = t & 31, warp = t >> 5;
    const int z = blockIdx.z;
    const int mblk = blockIdx.y * 128, nblk = blockIdx.x * 128;

    const float* Az = A + (size_t)(z / zdA) * sA + (size_t)(z % zdA) * sA2 + (size_t)mblk * lda;
    const float* Bz = B + (size_t)z * sB + (size_t)nblk * ldb;
    float* Cz = C + (size_t)(z / zdC) * sC + (size_t)(z % zdC) * sC2;

    const uint32_t sbase = smem_u32(sm);
    const int T = K >> 5;

    if (warp >= 4) {
        const int pt   = t - 128;
        const int prow = pt >> 3;
        const int pch  = pt & 7;

        for (int tt = 0; tt < T; tt++) {
            const int b = tt & 1;
            if (tt >= 2) asm volatile("bar.sync %0, 256;" :: "r"(3 + b));
            char* buf = sm + b * BUFSZ;
            const float* ap = Az + tt * 32 + pch * 4;
            const float* bp = Bz + tt * 32 + pch * 4;
            float4 fa[8], fb[8];
#pragma unroll
            for (int j = 0; j < 8; j++) {
                fa[j] = *(const float4*)(ap + (size_t)(j * 16 + prow) * lda);
                fb[j] = *(const float4*)(bp + (size_t)(j * 16 + prow) * ldb);
            }
#pragma unroll
            for (int j = 0; j < 8; j++) {
                const uint32_t off = sw64((uint32_t)((j * 16 + prow) * 64 + pch * 8));
                uint32_t p0, p1, p2, q0, q1, q2;
                split2<NL>(fa[j].x, fa[j].y, p0, p1, p2);
                split2<NL>(fa[j].z, fa[j].w, q0, q1, q2);
                *(uint2*)(buf + off)        = make_uint2(p0, q0);
                *(uint2*)(buf + 8192 + off) = make_uint2(p1, q1);
                if (NL == 3) *(uint2*)(buf + 16384 + off) = make_uint2(p2, q2);
                split2<NL>(fb[j].x, fb[j].y, p0, p1, p2);
                split2<NL>(fb[j].z, fb[j].w, q0, q1, q2);
                *(uint2*)(buf + 24576 + off)        = make_uint2(p0, q0);
                *(uint2*)(buf + 24576 + 8192 + off) = make_uint2(p1, q1);
                if (NL == 3) *(uint2*)(buf + 24576 + 16384 + off) = make_uint2(p2, q2);
            }
            asm volatile("bar.arrive %0, 256;" :: "r"(1 + b));
        }
        return;
    }

    const int wm = warp >> 1, wn = warp & 1;

    float acc[4][8][4];
#pragma unroll
    for (int mi = 0; mi < 4; mi++)
#pragma unroll
        for (int f = 0; f < 8; f++)
#pragma unroll
            for (int c = 0; c < 4; c++) acc[mi][f][c] = 0.f;

    const int a_row = wm * 64 + (lane & 15);
    const int a_kb  = (lane >> 4) << 4;
    const int b_row = wn * 64 + (lane & 7) + ((lane & 16) ? 8 : 0);
    const int b_kb  = (lane & 8) ? 16 : 0;

    for (int tt = 0; tt < T; tt++) {
        const int b = tt & 1;
        asm volatile("bar.sync %0, 256;" :: "r"(1 + b));
        const uint32_t bufb = sbase + b * BUFSZ;
#pragma unroll
        for (int ks = 0; ks < 2; ks++) {
            uint32_t afr[NL][4][4];
#pragma unroll
            for (int p = 0; p < NL; p++)
#pragma unroll
                for (int mi = 0; mi < 4; mi++)
                    ldmx4(afr[p][mi],
                          bufb + p * 8192 + sw64((uint32_t)((a_row + mi * 16) * 64 + ks * 32 + a_kb)));
            uint32_t bfr[2][8][2];
#define LOADB(slot, plane) do {                                                \
                const uint32_t _bb = bufb + 24576 + (plane) * 8192;            \
                _Pragma("unroll")                                              \
                for (int nj = 0; nj < 4; nj++) {                               \
                    uint32_t r[4];                                             \
                    ldmx4(r, _bb + sw64((uint32_t)((b_row + nj * 16) * 64 + ks * 32 + b_kb))); \
                    bfr[slot][nj * 2][0] = r[0]; bfr[slot][nj * 2][1] = r[1];  \
                    bfr[slot][nj * 2 + 1][0] = r[2]; bfr[slot][nj * 2 + 1][1] = r[3]; \
                }                                                              \
            } while (0)
            LOADB(0, 0);
#pragma unroll
            for (int ib = 0; ib < NL; ib++) {
                if (ib + 1 < NL) LOADB((ib + 1) & 1, ib + 1);
#pragma unroll
                for (int ia = 0; ia < NL - ib; ia++)
#pragma unroll
                    for (int mi = 0; mi < 4; mi++)
#pragma unroll
                        for (int f = 0; f < 8; f++)
                            mma16816(acc[mi][f], afr[ia][mi], bfr[ib & 1][f]);
            }
#undef LOADB
        }
        if (tt + 2 < T) asm volatile("bar.arrive %0, 256;" :: "r"(3 + b));
    }

    const int r0 = mblk + wm * 64 + (lane >> 2);
    const int c0 = nblk + wn * 64 + (lane & 3) * 2;
#pragma unroll
    for (int mi = 0; mi < 4; mi++) {
#pragma unroll
        for (int f = 0; f < 8; f++) {
            const int col = c0 + f * 8;
            float o[4];
#pragma unroll
            for (int c = 0; c < 4; c++) {
                float vv = acc[mi][f][c];
                if (EPI == 1) vv += __ldg(&bias[col + (c & 1)]);
                else if (EPI == 2) {
                    float ax = fabsf(vv * alpha);
                    float th = 1.f - __fdividef(2.f, __expf(2.f * ax) + 1.f);
                    vv = copysignf(th, vv);
                } else if (EPI == 3) {
                    vv += __ldg(&bias[col + (c & 1)]);
                    vv = vv > 0.f ? vv : 0.f;
                }
                o[c] = vv;
            }
            *(float2*)&Cz[(size_t)(r0 + mi * 16) * ldc + col]     = make_float2(o[0], o[1]);
            *(float2*)&Cz[(size_t)(r0 + mi * 16 + 8) * ldc + col] = make_float2(o[2], o[3]);
        }
    }
}

// generic transpose: src [z][R][C] -> dst [z][C][R]
__global__ void transpose_f(const float* __restrict__ src, float* __restrict__ dst,
                            int R, int C) {
    __shared__ float tl[32][33];
    const int z = blockIdx.z;
    const float* s = src + (size_t)z * R * C;
    float* d = dst + (size_t)z * R * C;
    const int r0 = blockIdx.y * 32, c0 = blockIdx.x * 32;
    const int tx = threadIdx.x, ty = threadIdx.y;
#pragma unroll
    for (int i = 0; i < 32; i += 8)
        tl[ty + i][tx] = s[(size_t)(r0 + ty + i) * C + c0 + tx];
    __syncthreads();
#pragma unroll
    for (int i = 0; i < 32; i += 8)
        d[(size_t)(c0 + ty + i) * R + r0 + tx] = tl[tx][ty + i];
}

// v [b][n][h*128+f] -> vt [z][f][n]
__global__ void transpose_v(const float* __restrict__ v, float* __restrict__ vt) {
    __shared__ float tl[32][33];
    const int z = blockIdx.z, b = z >> 2, h = z & 3;
    const int n0 = blockIdx.x * 32, f0 = blockIdx.y * 32;
    const float* src = v + (size_t)b * NN * 512 + (size_t)h * 128;
    float* dst = vt + (size_t)z * EE * NN;
    const int tx = threadIdx.x, ty = threadIdx.y;
#pragma unroll
    for (int i = 0; i < 32; i += 8)
        tl[ty + i][tx] = src[(size_t)(n0 + ty + i) * 512 + f0 + tx];
    __syncthreads();
#pragma unroll
    for (int i = 0; i < 32; i += 8)
        dst[(size_t)(f0 + ty + i) * NN + n0 + tx] = tl[tx][ty + i];
}

extern "C" void kernel_launch(void* const* d_in, const int* in_sizes, int n_in,
                              void* d_out, int out_size)
{
    const float* x   = (const float*)d_in[0];
    const float* W1  = (const float*)d_in[1];
    const float* b1  = (const float*)d_in[2];
    const float* wqW = (const float*)d_in[3];
    const float* wqb = (const float*)d_in[4];
    // d_in[5], d_in[6]: wk -- dead in the reference
    const float* wvW = (const float*)d_in[7];
    const float* wvb = (const float*)d_in[8];
    const float* W2  = (const float*)d_in[9];
    const float* b2  = (const float*)d_in[10];
    float* out = (float*)d_out;

    float *xt, *u, *emb, *q, *v, *vt, *wt, *wp, *mt, *attn, *hcat;
    cudaGetSymbolAddress((void**)&xt,   g_xt);
    cudaGetSymbolAddress((void**)&u,    g_u);
    cudaGetSymbolAddress((void**)&emb,  g_emb);
    cudaGetSymbolAddress((void**)&q,    g_q);
    cudaGetSymbolAddress((void**)&v,    g_v);
    cudaGetSymbolAddress((void**)&vt,   g_vt);
    cudaGetSymbolAddress((void**)&wt,   g_wt);
    cudaGetSymbolAddress((void**)&wp,   g_wp);
    cudaGetSymbolAddress((void**)&mt,   g_mt);
    cudaGetSymbolAddress((void**)&attn, g_attn);
    cudaGetSymbolAddress((void**)&hcat, g_hcat);

    cudaFuncSetAttribute(gemm_ws<3,0>, cudaFuncAttributeMaxDynamicSharedMemorySize, SMEM_BYTES);
    cudaFuncSetAttribute(gemm_ws<3,1>, cudaFuncAttributeMaxDynamicSharedMemorySize, SMEM_BYTES);
    cudaFuncSetAttribute(gemm_ws<3,2>, cudaFuncAttributeMaxDynamicSharedMemorySize, SMEM_BYTES);
    cudaFuncSetAttribute(gemm_ws<2,0>, cudaFuncAttributeMaxDynamicSharedMemorySize, SMEM_BYTES);
    cudaFuncSetAttribute(gemm_ws<2,3>, cudaFuncAttributeMaxDynamicSharedMemorySize, SMEM_BYTES);

    const float alpha = 0.08838834764831843f;  // 1/sqrt(128)
    const size_t ZX = (size_t)NN * EE;         // per-batch x/emb
    const size_t ZU = (size_t)EE * EE;         // per-z 128x128
    const size_t ZV = (size_t)EE * NN;         // per-z vt / per-b xt

    // xt[b][d][n] = x[b][n][d]
    transpose_f<<<dim3(4, 64, BB), dim3(32, 8)>>>(x, xt, NN, EE);

    // u[b] = W1 @ x_b^T : u[e][d] = sum_n W1[e][n] xt[d][n]      K=2048
    gemm_ws<3,0><<<dim3(1,1,BB), 256, SMEM_BYTES>>>(
        W1, 0, 0, 1, NN,  xt, ZV, NN,  nullptr,
        u, ZU, 0, 1, EE,  NN, 0.f);

    // emb[b] = x_b @ u_b^T + b1  (== info @ W1^T + b1)           K=128
    gemm_ws<3,1><<<dim3(1,16,BB), 256, SMEM_BYTES>>>(
        x, ZX, 0, 1, EE,  u, ZU, EE,  b1,
        emb, ZX, 0, 1, EE,  EE, 0.f);

    // q/v (all heads) = emb_b @ Wcat^T + bcat                    K=128
    gemm_ws<3,1><<<dim3(4,16,BB), 256, SMEM_BYTES>>>(
        emb, ZX, 0, 1, EE,  wqW, 0, EE,  wqb,
        q, (size_t)NN*512, 0, 1, 512,  EE, 0.f);
    gemm_ws<3,1><<<dim3(4,16,BB), 256, SMEM_BYTES>>>(
        emb, ZX, 0, 1, EE,  wvW, 0, EE,  wvb,
        v, (size_t)NN*512, 0, 1, 512,  EE, 0.f);

    transpose_v<<<dim3(64,4,BB*HH), dim3(32,8)>>>(v, vt);

    // wt[z] = x_b^T @ v_z : wt[d][f] = sum_n xt[d][n] vt[f][n]   K=2048
    gemm_ws<3,0><<<dim3(1,1,BB*HH), 256, SMEM_BYTES>>>(
        xt, ZV, 0, HH, NN,  vt, ZV, NN,  nullptr,
        wt, ZU, 0, 1, EE,  NN, 0.f);

    // wp[z] = wt[z]^T
    transpose_f<<<dim3(4, 4, BB*HH), dim3(32, 8)>>>(wt, wp, EE, EE);

    // mt[z] = x_b @ wp_z^T  (== info @ v, info symmetric)        K=128
    gemm_ws<3,0><<<dim3(1,16,BB*HH), 256, SMEM_BYTES>>>(
        x, ZX, 0, HH, EE,  wp, ZU, EE,  nullptr,
        mt, (size_t)NN*EE, 0, 1, EE,  EE, 0.f);

    // S5: attn[z] = tanh((q_z @ mt_z^T) * alpha)                 K=128
    gemm_ws<3,2><<<dim3(16,16,BB*HH), 256, SMEM_BYTES>>>(
        q, (size_t)NN*512, 128, HH, 512,  mt, (size_t)NN*EE, EE,  nullptr,
        attn, (size_t)NN*NN, 0, 1, NN,  EE, alpha);

    // S6: hcat[b][n][h*128+f] = attn_z @ vt_z^T                  K=2048
    gemm_ws<2,0><<<dim3(1,16,BB*HH), 256, SMEM_BYTES>>>(
        attn, (size_t)NN*NN, 0, 1, NN,  vt, ZV, NN,  nullptr,
        hcat, (size_t)NN*512, 128, HH, 512,  NN, 0.f);

    // S7: out[b] = relu(hcat_b @ W2^T + b2)                      K=512
    gemm_ws<2,3><<<dim3(1,16,BB), 256, SMEM_BYTES>>>(
        hcat, (size_t)NN*512, 0, 1, 512,  W2, 0, 512,  b2,
        out, ZX, 0, 1, EE,  512, 0.f);
}

// round 16
// speedup vs baseline: 2.1219x; 1.1695x over previous
#include <cuda_runtime.h>
#include <cstdint>
#include <math.h>

#define BB 8
#define NN 2048
#define EE 128
#define HH 4

static __device__ float g_xt    [(size_t)BB * EE * NN];           // x^T  [b][d][n]
static __device__ float g_upart [(size_t)BB * 8 * EE * EE];       // split-K partials of W1 x^T
static __device__ float g_u     [(size_t)BB * EE * EE];           // W1 x^T [b][e][d]
static __device__ float g_emb   [(size_t)BB * NN * EE];
static __device__ float g_q     [(size_t)BB * NN * (HH * EE)];
static __device__ float g_v     [(size_t)BB * NN * (HH * EE)];
static __device__ float g_vt    [(size_t)BB * HH * EE * NN];      // [z][f][n]
static __device__ float g_wtpart[(size_t)BB * HH * 8 * EE * EE];  // split-K partials of x^T v
static __device__ float g_wp    [(size_t)BB * HH * EE * EE];      // (x^T v)^T [z][f][d]
static __device__ float g_mt    [(size_t)BB * HH * NN * EE];
static __device__ float g_attn  [(size_t)BB * HH * NN * NN];
static __device__ float g_hcat  [(size_t)BB * NN * (HH * EE)];

__device__ __forceinline__ uint32_t smem_u32(const void* p) {
    uint32_t a;
    asm("{ .reg .u64 t; cvta.to.shared.u64 t, %1; cvt.u32.u64 %0, t; }" : "=r"(a) : "l"(p));
    return a;
}
__device__ __forceinline__ uint32_t sw64(uint32_t o) { return o ^ ((o >> 3) & 0x30); }

__device__ __forceinline__ void ldmx4(uint32_t* r, uint32_t addr) {
    asm volatile("ldmatrix.sync.aligned.m8n8.x4.shared.b16 {%0,%1,%2,%3}, [%4];"
                 : "=r"(r[0]), "=r"(r[1]), "=r"(r[2]), "=r"(r[3]) : "r"(addr));
}
__device__ __forceinline__ void mma16816(float* d, const uint32_t* a, const uint32_t* b) {
    asm volatile("mma.sync.aligned.m16n8k16.row.col.f32.bf16.bf16.f32 "
                 "{%0,%1,%2,%3}, {%4,%5,%6,%7}, {%8,%9}, {%0,%1,%2,%3};"
                 : "+f"(d[0]), "+f"(d[1]), "+f"(d[2]), "+f"(d[3])
                 : "r"(a[0]), "r"(a[1]), "r"(a[2]), "r"(a[3]), "r"(b[0]), "r"(b[1]));
}

// exact truncation split of a float pair into packed bf16x2 limbs
template <int NL>
__device__ __forceinline__ void split2(float f0, float f1, uint32_t& o0, uint32_t& o1, uint32_t& o2) {
    uint32_t u0 = __float_as_uint(f0), u1 = __float_as_uint(f1);
    float a0 = __uint_as_float(u0 & 0xFFFF0000u), a1 = __uint_as_float(u1 & 0xFFFF0000u);
    float r0 = f0 - a0, r1 = f1 - a1;                      // exact
    uint32_t v0 = __float_as_uint(r0), v1 = __float_as_uint(r1);
    o0 = __byte_perm(u0, u1, 0x7632);
    o1 = __byte_perm(v0, v1, 0x7632);
    if (NL == 3) {
        float b0 = __uint_as_float(v0 & 0xFFFF0000u), b1 = __uint_as_float(v1 & 0xFFFF0000u);
        o2 = __byte_perm(__float_as_uint(r0 - b0), __float_as_uint(r1 - b1), 0x7632); // exact
    }
}

// ---------------------------------------------------------------------------
// Warp-specialized limb GEMM.
// C tile[128x128] = epi(A*B^T); A [MxK] (lda), B [NnxK] (ldb), fp32 K-contig.
// warps 0..3 consumers (64x64 tiles), warps 4..7 producers.
// SPLITK=1: blockIdx.y = K-split index (M fixed to 128): A/B advance by
// blockIdx.y*K along K; C advances by blockIdx.y*sSpl.
// ---------------------------------------------------------------------------
#define BUFSZ 49152
#define SMEM_BYTES (2 * BUFSZ)

template <int NL, int EPI, int SPLITK>
__global__ void __launch_bounds__(256, 1)
gemm_ws(const float* __restrict__ A, size_t sA, size_t sA2, int zdA, int lda,
        const float* __restrict__ B, size_t sB, int ldb,
        const float* __restrict__ bias,
        float* __restrict__ C, size_t sC, size_t sC2, int zdC, int ldc,
        size_t sSpl, int K, float alpha)
{
    extern __shared__ __align__(128) char sm[];
    const int t = threadIdx.x;
    const int lane = t & 31, warp = t >> 5;
    const int z = blockIdx.z;
    const int mblk = SPLITK ? 0 : blockIdx.y * 128;
    const int nblk = blockIdx.x * 128;
    const size_t kofs = SPLITK ? (size_t)blockIdx.y * K : 0;

    const float* Az = A + (size_t)(z / zdA) * sA + (size_t)(z % zdA) * sA2
                        + (size_t)mblk * lda + kofs;
    const float* Bz = B + (size_t)z * sB + (size_t)nblk * ldb + kofs;
    float* Cz = C + (size_t)(z / zdC) * sC + (size_t)(z % zdC) * sC2
                  + (SPLITK ? (size_t)blockIdx.y * sSpl : 0);

    const uint32_t sbase = smem_u32(sm);
    const int T = K >> 5;

    if (warp >= 4) {
        const int pt   = t - 128;
        const int prow = pt >> 3;
        const int pch  = pt & 7;

        for (int tt = 0; tt < T; tt++) {
            const int b = tt & 1;
            if (tt >= 2) asm volatile("bar.sync %0, 256;" :: "r"(3 + b));
            char* buf = sm + b * BUFSZ;
            const float* ap = Az + tt * 32 + pch * 4;
            const float* bp = Bz + tt * 32 + pch * 4;
            float4 fa[8], fb[8];
#pragma unroll
            for (int j = 0; j < 8; j++) {
                fa[j] = *(const float4*)(ap + (size_t)(j * 16 + prow) * lda);
                fb[j] = *(const float4*)(bp + (size_t)(j * 16 + prow) * ldb);
            }
#pragma unroll
            for (int j = 0; j < 8; j++) {
                const uint32_t off = sw64((uint32_t)((j * 16 + prow) * 64 + pch * 8));
                uint32_t p0, p1, p2, q0, q1, q2;
                split2<NL>(fa[j].x, fa[j].y, p0, p1, p2);
                split2<NL>(fa[j].z, fa[j].w, q0, q1, q2);
                *(uint2*)(buf + off)        = make_uint2(p0, q0);
                *(uint2*)(buf + 8192 + off) = make_uint2(p1, q1);
                if (NL == 3) *(uint2*)(buf + 16384 + off) = make_uint2(p2, q2);
                split2<NL>(fb[j].x, fb[j].y, p0, p1, p2);
                split2<NL>(fb[j].z, fb[j].w, q0, q1, q2);
                *(uint2*)(buf + 24576 + off)        = make_uint2(p0, q0);
                *(uint2*)(buf + 24576 + 8192 + off) = make_uint2(p1, q1);
                if (NL == 3) *(uint2*)(buf + 24576 + 16384 + off) = make_uint2(p2, q2);
            }
            asm volatile("bar.arrive %0, 256;" :: "r"(1 + b));
        }
        return;
    }

    const int wm = warp >> 1, wn = warp & 1;

    float acc[4][8][4];
#pragma unroll
    for (int mi = 0; mi < 4; mi++)
#pragma unroll
        for (int f = 0; f < 8; f++)
#pragma unroll
            for (int c = 0; c < 4; c++) acc[mi][f][c] = 0.f;

    const int a_row = wm * 64 + (lane & 15);
    const int a_kb  = (lane >> 4) << 4;
    const int b_row = wn * 64 + (lane & 7) + ((lane & 16) ? 8 : 0);
    const int b_kb  = (lane & 8) ? 16 : 0;

    for (int tt = 0; tt < T; tt++) {
        const int b = tt & 1;
        asm volatile("bar.sync %0, 256;" :: "r"(1 + b));
        const uint32_t bufb = sbase + b * BUFSZ;
#pragma unroll
        for (int ks = 0; ks < 2; ks++) {
            uint32_t afr[NL][4][4];
#pragma unroll
            for (int p = 0; p < NL; p++)
#pragma unroll
                for (int mi = 0; mi < 4; mi++)
                    ldmx4(afr[p][mi],
                          bufb + p * 8192 + sw64((uint32_t)((a_row + mi * 16) * 64 + ks * 32 + a_kb)));
            uint32_t bfr[2][8][2];
#define LOADB(slot, plane) do {                                                \
                const uint32_t _bb = bufb + 24576 + (plane) * 8192;            \
                _Pragma("unroll")                                              \
                for (int nj = 0; nj < 4; nj++) {                               \
                    uint32_t r[4];                                             \
                    ldmx4(r, _bb + sw64((uint32_t)((b_row + nj * 16) * 64 + ks * 32 + b_kb))); \
                    bfr[slot][nj * 2][0] = r[0]; bfr[slot][nj * 2][1] = r[1];  \
                    bfr[slot][nj * 2 + 1][0] = r[2]; bfr[slot][nj * 2 + 1][1] = r[3]; \
                }                                                              \
            } while (0)
            LOADB(0, 0);
#pragma unroll
            for (int ib = 0; ib < NL; ib++) {
                if (ib + 1 < NL) LOADB((ib + 1) & 1, ib + 1);
#pragma unroll
                for (int ia = 0; ia < NL - ib; ia++)
#pragma unroll
                    for (int mi = 0; mi < 4; mi++)
#pragma unroll
                        for (int f = 0; f < 8; f++)
                            mma16816(acc[mi][f], afr[ia][mi], bfr[ib & 1][f]);
            }
#undef LOADB
        }
        if (tt + 2 < T) asm volatile("bar.arrive %0, 256;" :: "r"(3 + b));
    }

    const int r0 = mblk + wm * 64 + (lane >> 2);
    const int c0 = nblk + wn * 64 + (lane & 3) * 2;
#pragma unroll
    for (int mi = 0; mi < 4; mi++) {
#pragma unroll
        for (int f = 0; f < 8; f++) {
            const int col = c0 + f * 8;
            float o[4];
#pragma unroll
            for (int c = 0; c < 4; c++) {
                float vv = acc[mi][f][c];
                if (EPI == 1) vv += __ldg(&bias[col + (c & 1)]);
                else if (EPI == 2) {
                    float ax = fabsf(vv * alpha);
                    float th = 1.f - __fdividef(2.f, __expf(2.f * ax) + 1.f);
                    vv = copysignf(th, vv);
                } else if (EPI == 3) {
                    vv += __ldg(&bias[col + (c & 1)]);
                    vv = vv > 0.f ? vv : 0.f;
                }
                o[c] = vv;
            }
            *(float2*)&Cz[(size_t)(r0 + mi * 16) * ldc + col]     = make_float2(o[0], o[1]);
            *(float2*)&Cz[(size_t)(r0 + mi * 16 + 8) * ldc + col] = make_float2(o[2], o[3]);
        }
    }
}

// generic transpose: src [z][R][C] -> dst [z][C][R]
__global__ void transpose_f(const float* __restrict__ src, float* __restrict__ dst,
                            int R, int C) {
    __shared__ float tl[32][33];
    const int z = blockIdx.z;
    const float* s = src + (size_t)z * R * C;
    float* d = dst + (size_t)z * R * C;
    const int r0 = blockIdx.y * 32, c0 = blockIdx.x * 32;
    const int tx = threadIdx.x, ty = threadIdx.y;
#pragma unroll
    for (int i = 0; i < 32; i += 8)
        tl[ty + i][tx] = s[(size_t)(r0 + ty + i) * C + c0 + tx];
    __syncthreads();
#pragma unroll
    for (int i = 0; i < 32; i += 8)
        d[(size_t)(c0 + ty + i) * R + r0 + tx] = tl[tx][ty + i];
}

// v [b][n][h*128+f] -> vt [z][f][n]
__global__ void transpose_v(const float* __restrict__ v, float* __restrict__ vt) {
    __shared__ float tl[32][33];
    const int z = blockIdx.z, b = z >> 2, h = z & 3;
    const int n0 = blockIdx.x * 32, f0 = blockIdx.y * 32;
    const float* src = v + (size_t)b * NN * 512 + (size_t)h * 128;
    float* dst = vt + (size_t)z * EE * NN;
    const int tx = threadIdx.x, ty = threadIdx.y;
#pragma unroll
    for (int i = 0; i < 32; i += 8)
        tl[ty + i][tx] = src[(size_t)(n0 + ty + i) * 512 + f0 + tx];
    __syncthreads();
#pragma unroll
    for (int i = 0; i < 32; i += 8)
        dst[(size_t)(f0 + ty + i) * NN + n0 + tx] = tl[tx][ty + i];
}

// sum 8 split-K partials: out[z][i] = sum_s in[z][s][i]   (i over 128*128)
__global__ void reduce8(const float* __restrict__ in, float* __restrict__ out) {
    const int z = blockIdx.z;
    const int i = blockIdx.x * 256 + threadIdx.x;
    const float* p = in + ((size_t)z * 8) * 16384 + i;
    float a = 0.f;
#pragma unroll
    for (int s = 0; s < 8; s++) a += p[s * 16384];
    out[(size_t)z * 16384 + i] = a;
}

// sum 8 split-K partials AND transpose: out[z][f][d] = sum_s in[z][s][d][f]
__global__ void reduce8_t(const float* __restrict__ in, float* __restrict__ out) {
    __shared__ float tl[32][33];
    const int z = blockIdx.z;
    const float* p = in + (size_t)z * 8 * 16384;
    float* o = out + (size_t)z * 16384;
    const int d0 = blockIdx.y * 32, f0 = blockIdx.x * 32;
    const int tx = threadIdx.x, ty = threadIdx.y;
#pragma unroll
    for (int i = 0; i < 32; i += 8) {
        float a = 0.f;
#pragma unroll
        for (int s = 0; s < 8; s++)
            a += p[s * 16384 + (size_t)(d0 + ty + i) * EE + f0 + tx];
        tl[ty + i][tx] = a;
    }
    __syncthreads();
#pragma unroll
    for (int i = 0; i < 32; i += 8)
        o[(size_t)(f0 + ty + i) * EE + d0 + tx] = tl[tx][ty + i];
}

extern "C" void kernel_launch(void* const* d_in, const int* in_sizes, int n_in,
                              void* d_out, int out_size)
{
    const float* x   = (const float*)d_in[0];
    const float* W1  = (const float*)d_in[1];
    const float* b1  = (const float*)d_in[2];
    const float* wqW = (const float*)d_in[3];
    const float* wqb = (const float*)d_in[4];
    // d_in[5], d_in[6]: wk -- dead in the reference
    const float* wvW = (const float*)d_in[7];
    const float* wvb = (const float*)d_in[8];
    const float* W2  = (const float*)d_in[9];
    const float* b2  = (const float*)d_in[10];
    float* out = (float*)d_out;

    float *xt, *upart, *u, *emb, *q, *v, *vt, *wtpart, *wp, *mt, *attn, *hcat;
    cudaGetSymbolAddress((void**)&xt,     g_xt);
    cudaGetSymbolAddress((void**)&upart,  g_upart);
    cudaGetSymbolAddress((void**)&u,      g_u);
    cudaGetSymbolAddress((void**)&emb,    g_emb);
    cudaGetSymbolAddress((void**)&q,      g_q);
    cudaGetSymbolAddress((void**)&v,      g_v);
    cudaGetSymbolAddress((void**)&vt,     g_vt);
    cudaGetSymbolAddress((void**)&wtpart, g_wtpart);
    cudaGetSymbolAddress((void**)&wp,     g_wp);
    cudaGetSymbolAddress((void**)&mt,     g_mt);
    cudaGetSymbolAddress((void**)&attn,   g_attn);
    cudaGetSymbolAddress((void**)&hcat,   g_hcat);

    cudaFuncSetAttribute(gemm_ws<3,0,0>, cudaFuncAttributeMaxDynamicSharedMemorySize, SMEM_BYTES);
    cudaFuncSetAttribute(gemm_ws<3,1,0>, cudaFuncAttributeMaxDynamicSharedMemorySize, SMEM_BYTES);
    cudaFuncSetAttribute(gemm_ws<3,2,0>, cudaFuncAttributeMaxDynamicSharedMemorySize, SMEM_BYTES);
    cudaFuncSetAttribute(gemm_ws<2,0,0>, cudaFuncAttributeMaxDynamicSharedMemorySize, SMEM_BYTES);
    cudaFuncSetAttribute(gemm_ws<2,3,0>, cudaFuncAttributeMaxDynamicSharedMemorySize, SMEM_BYTES);
    cudaFuncSetAttribute(gemm_ws<3,0,1>, cudaFuncAttributeMaxDynamicSharedMemorySize, SMEM_BYTES);

    const float alpha = 0.08838834764831843f;  // 1/sqrt(128)
    const size_t ZX = (size_t)NN * EE;         // per-batch x/emb
    const size_t ZU = (size_t)EE * EE;         // 128x128
    const size_t ZV = (size_t)EE * NN;         // per-z vt / per-b xt

    // xt[b][d][n] = x[b][n][d]
    transpose_f<<<dim3(4, 64, BB), dim3(32, 8)>>>(x, xt, NN, EE);

    // u = W1 @ x^T, split-K 8 x 256: upart[b][s][e][d]
    gemm_ws<3,0,1><<<dim3(1,8,BB), 256, SMEM_BYTES>>>(
        W1, 0, 0, 1, NN,  xt, ZV, NN,  nullptr,
        upart, ZU * 8, 0, 1, EE,  ZU, 256, 0.f);
    reduce8<<<dim3(64,1,BB), 256>>>(upart, u);

    // emb[b] = x_b @ u_b^T + b1  (== info @ W1^T + b1)            K=128
    gemm_ws<3,1,0><<<dim3(1,16,BB), 256, SMEM_BYTES>>>(
        x, ZX, 0, 1, EE,  u, ZU, EE,  b1,
        emb, ZX, 0, 1, EE,  0, EE, 0.f);

    // q/v (all heads) = emb_b @ Wcat^T + bcat                     K=128
    gemm_ws<3,1,0><<<dim3(4,16,BB), 256, SMEM_BYTES>>>(
        emb, ZX, 0, 1, EE,  wqW, 0, EE,  wqb,
        q, (size_t)NN*512, 0, 1, 512,  0, EE, 0.f);
    gemm_ws<3,1,0><<<dim3(4,16,BB), 256, SMEM_BYTES>>>(
        emb, ZX, 0, 1, EE,  wvW, 0, EE,  wvb,
        v, (size_t)NN*512, 0, 1, 512,  0, EE, 0.f);

    transpose_v<<<dim3(64,4,BB*HH), dim3(32,8)>>>(v, vt);

    // wt = x^T @ v, split-K 8 x 256: wtpart[z][s][d][f]
    gemm_ws<3,0,1><<<dim3(1,8,BB*HH), 256, SMEM_BYTES>>>(
        xt, ZV, 0, HH, NN,  vt, ZV, NN,  nullptr,
        wtpart, ZU * 8, 0, 1, EE,  ZU, 256, 0.f);
    // reduce + transpose: wp[z][f][d] = sum_s wtpart[z][s][d][f]
    reduce8_t<<<dim3(4,4,BB*HH), dim3(32,8)>>>(wtpart, wp);

    // mt[z] = x_b @ wp_z^T  (== info @ v, info symmetric)         K=128
    gemm_ws<3,0,0><<<dim3(1,16,BB*HH), 256, SMEM_BYTES>>>(
        x, ZX, 0, HH, EE,  wp, ZU, EE,  nullptr,
        mt, (size_t)NN*EE, 0, 1, EE,  0, EE, 0.f);

    // S5: attn[z] = tanh((q_z @ mt_z^T) * alpha)                  K=128
    gemm_ws<3,2,0><<<dim3(16,16,BB*HH), 256, SMEM_BYTES>>>(
        q, (size_t)NN*512, 128, HH, 512,  mt, (size_t)NN*EE, EE,  nullptr,
        attn, (size_t)NN*NN, 0, 1, NN,  0, EE, alpha);

    // S6: hcat[b][n][h*128+f] = attn_z @ vt_z^T                   K=2048
    gemm_ws<2,0,0><<<dim3(1,16,BB*HH), 256, SMEM_BYTES>>>(
        attn, (size_t)NN*NN, 0, 1, NN,  vt, ZV, NN,  nullptr,
        hcat, (size_t)NN*512, 128, HH, 512,  0, NN, 0.f);

    // S7: out[b] = relu(hcat_b @ W2^T + b2)                       K=512
    gemm_ws<2,3,0><<<dim3(1,16,BB), 256, SMEM_BYTES>>>(
        hcat, (size_t)NN*512, 0, 1, 512,  W2, 0, 512,  b2,
        out, ZX, 0, 1, EE,  0, 512, 0.f);
}